// round 3
// baseline (speedup 1.0000x reference)
#include <cuda_runtime.h>
#include <math.h>

#define SS 1024
#define DM 1024
#define NHQ 16
#define NKVH 4
#define HDIM 64
#define NE 64
#define TOPK 6
#define HE 512
#define NPAIR (SS*TOPK)

// ---------------- scratch (device globals; no allocation) ----------------
__device__ float g_hx[SS*DM];
__device__ float g_q[SS*NHQ*HDIM];
__device__ float g_k[SS*NKVH*HDIM];
__device__ float g_v[SS*NKVH*HDIM];
__device__ float g_attn[SS*NHQ*HDIM];
__device__ float g_o[SS*DM];
__device__ float g_h[SS*DM];
__device__ float g_z[SS*DM];
__device__ float g_logits[SS*NE];
__device__ float g_pairw[NPAIR];
__device__ int   g_cnt[NE];
__device__ int   g_list[NE*SS];
__device__ float g_gbuf[(size_t)NPAIR*HE];   // per-pair gated hidden
__device__ float g_g2[(size_t)NPAIR*DM];     // per-pair expert output
__device__ float g_a1[SS*HE];
__device__ float g_a3[SS*HE];
__device__ float g_sh[SS*DM];

// ---------------- rmsnorm: one block per token ----------------
__global__ __launch_bounds__(256) void rmsnorm_k(const float* __restrict__ x,
                                                 const float* __restrict__ w,
                                                 float* __restrict__ out) {
    int t = blockIdx.x;
    int tid = threadIdx.x;
    float4 xv = *(const float4*)&x[(size_t)t*DM + tid*4];
    float ss = xv.x*xv.x + xv.y*xv.y + xv.z*xv.z + xv.w*xv.w;
    #pragma unroll
    for (int off = 16; off; off >>= 1) ss += __shfl_xor_sync(0xffffffffu, ss, off);
    __shared__ float red[8];
    if ((tid & 31) == 0) red[tid >> 5] = ss;
    __syncthreads();
    float tot = 0.f;
    #pragma unroll
    for (int i = 0; i < 8; i++) tot += red[i];
    float r = rsqrtf(tot * (1.0f/DM) + 1e-5f);
    float4 wv = *(const float4*)&w[tid*4];
    float4 ov;
    ov.x = wv.x * (xv.x * r); ov.y = wv.y * (xv.y * r);
    ov.z = wv.z * (xv.z * r); ov.w = wv.w * (xv.w * r);
    *(float4*)&out[(size_t)t*DM + tid*4] = ov;
}

// ---------------- generic fp32 GEMM: C(MxN) = A(MxK) @ B(KxN), all row-major.
// 64x64 tile, BK=16, 256 threads, 4x4 per thread. M,N,K multiples of 64/64/16.
__global__ __launch_bounds__(256) void gemm64(const float* __restrict__ A,
                                              const float* __restrict__ B,
                                              float* __restrict__ C,
                                              int M, int N, int K) {
    __shared__ float As[16][64];
    __shared__ float Bs[16][64];
    int tid = threadIdx.x;
    int tx = tid & 15, ty = tid >> 4;
    int m0 = blockIdx.y * 64, n0 = blockIdx.x * 64;
    int ar = tid >> 2;            // 0..63
    int ac = (tid & 3) * 4;       // 0..12
    int br = tid >> 4;            // 0..15
    int bc = (tid & 15) * 4;      // 0..60
    float acc[4][4] = {};
    for (int k0 = 0; k0 < K; k0 += 16) {
        float4 av = *(const float4*)&A[(size_t)(m0 + ar)*K + k0 + ac];
        float4 bv = *(const float4*)&B[(size_t)(k0 + br)*N + n0 + bc];
        As[ac+0][ar] = av.x; As[ac+1][ar] = av.y;
        As[ac+2][ar] = av.z; As[ac+3][ar] = av.w;
        *(float4*)&Bs[br][bc] = bv;
        __syncthreads();
        #pragma unroll
        for (int k = 0; k < 16; k++) {
            float4 a = *(const float4*)&As[k][ty*4];
            float4 b = *(const float4*)&Bs[k][tx*4];
            float aa[4] = {a.x,a.y,a.z,a.w};
            float bb[4] = {b.x,b.y,b.z,b.w};
            #pragma unroll
            for (int i = 0; i < 4; i++)
                #pragma unroll
                for (int j = 0; j < 4; j++)
                    acc[i][j] += aa[i]*bb[j];
        }
        __syncthreads();
    }
    #pragma unroll
    for (int i = 0; i < 4; i++) {
        float4 ov = make_float4(acc[i][0],acc[i][1],acc[i][2],acc[i][3]);
        *(float4*)&C[(size_t)(m0 + ty*4 + i)*N + n0 + tx*4] = ov;
    }
}

// ---------------- q/k rmsnorm + rope: one warp per (token, head) ----------------
__global__ __launch_bounds__(256) void qknorm_rope(const float* __restrict__ qw,
                                                   const float* __restrict__ kw,
                                                   const float* __restrict__ cosb,
                                                   const float* __restrict__ sinb) {
    int gw = (blockIdx.x * blockDim.x + threadIdx.x) >> 5;
    int lane = threadIdx.x & 31;
    if (gw >= SS * (NHQ + NKVH)) return;
    int t = gw / (NHQ + NKVH);
    int hh = gw % (NHQ + NKVH);
    float* base;
    const float* w;
    if (hh < NHQ) { base = &g_q[(size_t)t*(NHQ*HDIM) + hh*HDIM]; w = qw; }
    else          { base = &g_k[(size_t)t*(NKVH*HDIM) + (hh-NHQ)*HDIM]; w = kw; }
    int d0 = lane * 2;
    float v0 = base[d0], v1 = base[d0+1];
    float ss = v0*v0 + v1*v1;
    #pragma unroll
    for (int off = 16; off; off >>= 1) ss += __shfl_xor_sync(0xffffffffu, ss, off);
    float r = rsqrtf(ss * (1.0f/HDIM) + 1e-5f);
    float n0 = v0 * r * w[d0];
    float n1 = v1 * r * w[d0+1];
    float c = cosb[t*(HDIM/2) + lane];
    float s = sinb[t*(HDIM/2) + lane];
    base[d0]   = n0*c - n1*s;
    base[d0+1] = n0*s + n1*c;
}

// ---------------- flash attention, fp32, causal, GQA 4:1 ----------------
#define FLASH_SMEM (4*64*65*4)
__global__ __launch_bounds__(256) void flash_attn() {
    extern __shared__ float sm[];
    float* Qs = sm;
    float* Ks = sm + 64*65;
    float* Vs = sm + 2*64*65;
    float* Ps = sm + 3*64*65;
    int qt = blockIdx.x, h = blockIdx.y;
    int kvh = h >> 2;
    int q0 = qt * 64;
    int tid = threadIdx.x;
    int tx = tid & 15, ty = tid >> 4;
    {
        int r = tid >> 2, c = (tid & 3) * 16;
        const float* src = &g_q[(size_t)(q0 + r)*(NHQ*HDIM) + h*HDIM + c];
        #pragma unroll
        for (int i = 0; i < 16; i += 4) {
            float4 vq = *(const float4*)(src + i);
            Qs[r*65+c+i]   = vq.x; Qs[r*65+c+i+1] = vq.y;
            Qs[r*65+c+i+2] = vq.z; Qs[r*65+c+i+3] = vq.w;
        }
    }
    float O[4][4] = {};
    float m_i[4] = {-1e30f,-1e30f,-1e30f,-1e30f};
    float l_i[4] = {};
    __syncthreads();
    for (int kt = 0; kt <= qt; kt++) {
        int k0 = kt * 64;
        {
            int r = tid >> 2, c = (tid & 3) * 16;
            const float* ksrc = &g_k[(size_t)(k0 + r)*(NKVH*HDIM) + kvh*HDIM + c];
            const float* vsrc = &g_v[(size_t)(k0 + r)*(NKVH*HDIM) + kvh*HDIM + c];
            #pragma unroll
            for (int i = 0; i < 16; i += 4) {
                float4 a = *(const float4*)(ksrc + i);
                float4 b = *(const float4*)(vsrc + i);
                Ks[r*65+c+i]=a.x; Ks[r*65+c+i+1]=a.y; Ks[r*65+c+i+2]=a.z; Ks[r*65+c+i+3]=a.w;
                Vs[r*65+c+i]=b.x; Vs[r*65+c+i+1]=b.y; Vs[r*65+c+i+2]=b.z; Vs[r*65+c+i+3]=b.w;
            }
        }
        __syncthreads();
        float s[4][4] = {};
        #pragma unroll 8
        for (int d = 0; d < 64; d++) {
            float qv[4], kv[4];
            #pragma unroll
            for (int i = 0; i < 4; i++) qv[i] = Qs[(ty*4+i)*65 + d];
            #pragma unroll
            for (int j = 0; j < 4; j++) kv[j] = Ks[(tx*4+j)*65 + d];
            #pragma unroll
            for (int i = 0; i < 4; i++)
                #pragma unroll
                for (int j = 0; j < 4; j++)
                    s[i][j] += qv[i]*kv[j];
        }
        const float sc = 0.125f;  // 1/sqrt(64)
        if (kt == qt) {
            #pragma unroll
            for (int i = 0; i < 4; i++)
                #pragma unroll
                for (int j = 0; j < 4; j++)
                    s[i][j] = (tx*4+j <= ty*4+i) ? s[i][j]*sc : -1e30f;
        } else {
            #pragma unroll
            for (int i = 0; i < 4; i++)
                #pragma unroll
                for (int j = 0; j < 4; j++)
                    s[i][j] *= sc;
        }
        #pragma unroll
        for (int i = 0; i < 4; i++) {
            float mx = fmaxf(fmaxf(s[i][0],s[i][1]), fmaxf(s[i][2],s[i][3]));
            mx = fmaxf(mx, __shfl_xor_sync(0xffffffffu, mx, 1));
            mx = fmaxf(mx, __shfl_xor_sync(0xffffffffu, mx, 2));
            mx = fmaxf(mx, __shfl_xor_sync(0xffffffffu, mx, 4));
            mx = fmaxf(mx, __shfl_xor_sync(0xffffffffu, mx, 8));
            float mn = fmaxf(m_i[i], mx);
            float scale = __expf(m_i[i] - mn);
            float rs = 0.f;
            #pragma unroll
            for (int j = 0; j < 4; j++) { float p = __expf(s[i][j]-mn); s[i][j]=p; rs += p; }
            rs += __shfl_xor_sync(0xffffffffu, rs, 1);
            rs += __shfl_xor_sync(0xffffffffu, rs, 2);
            rs += __shfl_xor_sync(0xffffffffu, rs, 4);
            rs += __shfl_xor_sync(0xffffffffu, rs, 8);
            l_i[i] = l_i[i]*scale + rs;
            m_i[i] = mn;
            #pragma unroll
            for (int j = 0; j < 4; j++) {
                O[i][j] *= scale;
                Ps[(ty*4+i)*65 + tx*4+j] = s[i][j];
            }
        }
        __syncthreads();
        #pragma unroll 4
        for (int jj = 0; jj < 64; jj++) {
            float pv[4], vv[4];
            #pragma unroll
            for (int i = 0; i < 4; i++) pv[i] = Ps[(ty*4+i)*65 + jj];
            #pragma unroll
            for (int j = 0; j < 4; j++) vv[j] = Vs[jj*65 + tx*4+j];
            #pragma unroll
            for (int i = 0; i < 4; i++)
                #pragma unroll
                for (int j = 0; j < 4; j++)
                    O[i][j] += pv[i]*vv[j];
        }
        __syncthreads();
    }
    #pragma unroll
    for (int i = 0; i < 4; i++) {
        float inv = 1.f / l_i[i];
        #pragma unroll
        for (int j = 0; j < 4; j++)
            g_attn[(size_t)(q0+ty*4+i)*(NHQ*HDIM) + h*HDIM + tx*4+j] = O[i][j]*inv;
    }
}

// ---------------- residual add: h = x + o ----------------
__global__ __launch_bounds__(256) void add_k(const float* __restrict__ x) {
    size_t i = ((size_t)blockIdx.x*256 + threadIdx.x)*4;
    float4 a = *(const float4*)&x[i];
    float4 b = *(const float4*)&g_o[i];
    a.x += b.x; a.y += b.y; a.z += b.z; a.w += b.w;
    *(float4*)&g_h[i] = a;
}

// ---------------- routing: top-6 + expert list build; one warp/token ----------------
__global__ void zero_cnt_k() { if (threadIdx.x < NE) g_cnt[threadIdx.x] = 0; }

__global__ void route_k() {
    int t = blockIdx.x;
    int lane = threadIdx.x;
    float v0 = g_logits[t*NE + lane];
    float v1 = g_logits[t*NE + 32 + lane];
    float selv[TOPK]; int seli[TOPK];
    #pragma unroll
    for (int it = 0; it < TOPK; it++) {
        float best = (v0 >= v1) ? v0 : v1;
        int   bi   = (v0 >= v1) ? lane : lane + 32;
        #pragma unroll
        for (int off = 16; off; off >>= 1) {
            float ov = __shfl_xor_sync(0xffffffffu, best, off);
            int   oi = __shfl_xor_sync(0xffffffffu, bi, off);
            if (ov > best || (ov == best && oi < bi)) { best = ov; bi = oi; }
        }
        selv[it] = best; seli[it] = bi;
        if (bi == lane)      v0 = -1e30f;
        if (bi == lane + 32) v1 = -1e30f;
    }
    if (lane < TOPK) {
        float sum = 0.f;
        #pragma unroll
        for (int i = 0; i < TOPK; i++) sum += __expf(selv[i] - selv[0]);
        float w = __expf(selv[lane] - selv[0]) / sum;
        int e = seli[lane];
        int pos = atomicAdd(&g_cnt[e], 1);
        g_list[e*SS + pos] = t*TOPK + lane;
        g_pairw[t*TOPK + lane] = w;
    }
}

// ---------------- grouped GEMM1: g[p] = silu(z_t@W1_e)*(z_t@W3_e)*w_p ----------------
// grid.x = NE * 8 (HE/64 n-tiles). BM=32 tokens, BN=64, BK=16.
__global__ __launch_bounds__(256) void moe_gemm1(const float* __restrict__ w1e,
                                                 const float* __restrict__ w3e) {
    int e  = blockIdx.x >> 3;
    int n0 = (blockIdx.x & 7) * 64;
    int n = g_cnt[e];
    if (n == 0) return;
    const int* lst = &g_list[e*SS];
    const float* W1 = w1e + (size_t)e * DM * HE;
    const float* W3 = w3e + (size_t)e * DM * HE;
    __shared__ float Zs[16][32];
    __shared__ float W1s[16][64];
    __shared__ float W3s[16][64];
    __shared__ int s_p[32];
    int tid = threadIdx.x;
    int tx = tid & 15, ty = tid >> 4;
    int zr = tid >> 3, zc = (tid & 7) * 2;
    int wr = tid >> 4, wc = (tid & 15) * 4;
    for (int m0 = 0; m0 < n; m0 += 32) {
        if (tid < 32) s_p[tid] = (m0 + tid < n) ? lst[m0 + tid] : -1;
        __syncthreads();
        int pz = s_p[zr];
        const float* zrow = &g_z[(size_t)(pz < 0 ? 0 : pz / TOPK) * DM];
        float a1[2][4] = {}; float a3[2][4] = {};
        for (int k0 = 0; k0 < DM; k0 += 16) {
            float2 zv = *(const float2*)&zrow[k0 + zc];
            float4 b1v = *(const float4*)&W1[(size_t)(k0 + wr)*HE + n0 + wc];
            float4 b3v = *(const float4*)&W3[(size_t)(k0 + wr)*HE + n0 + wc];
            Zs[zc][zr] = zv.x; Zs[zc+1][zr] = zv.y;
            *(float4*)&W1s[wr][wc] = b1v;
            *(float4*)&W3s[wr][wc] = b3v;
            __syncthreads();
            #pragma unroll
            for (int k = 0; k < 16; k++) {
                float z0 = Zs[k][ty*2], z1 = Zs[k][ty*2+1];
                float4 b1 = *(const float4*)&W1s[k][tx*4];
                float4 b3 = *(const float4*)&W3s[k][tx*4];
                a1[0][0]+=z0*b1.x; a1[0][1]+=z0*b1.y; a1[0][2]+=z0*b1.z; a1[0][3]+=z0*b1.w;
                a1[1][0]+=z1*b1.x; a1[1][1]+=z1*b1.y; a1[1][2]+=z1*b1.z; a1[1][3]+=z1*b1.w;
                a3[0][0]+=z0*b3.x; a3[0][1]+=z0*b3.y; a3[0][2]+=z0*b3.z; a3[0][3]+=z0*b3.w;
                a3[1][0]+=z1*b3.x; a3[1][1]+=z1*b3.y; a3[1][2]+=z1*b3.z; a3[1][3]+=z1*b3.w;
            }
            __syncthreads();
        }
        #pragma unroll
        for (int i = 0; i < 2; i++) {
            int p = s_p[ty*2 + i];
            if (p >= 0) {
                float w = g_pairw[p];
                float4 ov;
                float x0 = a1[i][0], x1 = a1[i][1], x2 = a1[i][2], x3 = a1[i][3];
                ov.x = (x0/(1.f+__expf(-x0))) * a3[i][0] * w;
                ov.y = (x1/(1.f+__expf(-x1))) * a3[i][1] * w;
                ov.z = (x2/(1.f+__expf(-x2))) * a3[i][2] * w;
                ov.w = (x3/(1.f+__expf(-x3))) * a3[i][3] * w;
                *(float4*)&g_gbuf[(size_t)p*HE + n0 + tx*4] = ov;
            }
        }
        __syncthreads();
    }
}

// ---------------- grouped GEMM2: g2[p] = g[p] @ W2_e ----------------
// grid.x = NE * 16 (DM/64 n-tiles). K=HE=512.
__global__ __launch_bounds__(256) void moe_gemm2(const float* __restrict__ w2e) {
    int e  = blockIdx.x >> 4;
    int n0 = (blockIdx.x & 15) * 64;
    int n = g_cnt[e];
    if (n == 0) return;
    const int* lst = &g_list[e*SS];
    const float* W2 = w2e + (size_t)e * HE * DM;
    __shared__ float Zs[16][32];
    __shared__ float Ws[16][64];
    __shared__ int s_p[32];
    int tid = threadIdx.x;
    int tx = tid & 15, ty = tid >> 4;
    int zr = tid >> 3, zc = (tid & 7) * 2;
    int wr = tid >> 4, wc = (tid & 15) * 4;
    for (int m0 = 0; m0 < n; m0 += 32) {
        if (tid < 32) s_p[tid] = (m0 + tid < n) ? lst[m0 + tid] : -1;
        __syncthreads();
        int pz = s_p[zr];
        const float* arow = &g_gbuf[(size_t)(pz < 0 ? 0 : pz) * HE];
        float acc[2][4] = {};
        for (int k0 = 0; k0 < HE; k0 += 16) {
            float2 zv = *(const float2*)&arow[k0 + zc];
            float4 wv = *(const float4*)&W2[(size_t)(k0 + wr)*DM + n0 + wc];
            Zs[zc][zr] = zv.x; Zs[zc+1][zr] = zv.y;
            *(float4*)&Ws[wr][wc] = wv;
            __syncthreads();
            #pragma unroll
            for (int k = 0; k < 16; k++) {
                float z0 = Zs[k][ty*2], z1 = Zs[k][ty*2+1];
                float4 b = *(const float4*)&Ws[k][tx*4];
                acc[0][0]+=z0*b.x; acc[0][1]+=z0*b.y; acc[0][2]+=z0*b.z; acc[0][3]+=z0*b.w;
                acc[1][0]+=z1*b.x; acc[1][1]+=z1*b.y; acc[1][2]+=z1*b.z; acc[1][3]+=z1*b.w;
            }
            __syncthreads();
        }
        #pragma unroll
        for (int i = 0; i < 2; i++) {
            int p = s_p[ty*2 + i];
            if (p >= 0) {
                float4 ov = make_float4(acc[i][0],acc[i][1],acc[i][2],acc[i][3]);
                *(float4*)&g_g2[(size_t)p*DM + n0 + tx*4] = ov;
            }
        }
        __syncthreads();
    }
}

// ---------------- shared expert silu*mul ----------------
__global__ __launch_bounds__(256) void silu_mul_k() {
    size_t i = ((size_t)blockIdx.x*256 + threadIdx.x)*4;
    float4 a = *(const float4*)&g_a1[i];
    float4 b = *(const float4*)&g_a3[i];
    a.x = (a.x/(1.f+__expf(-a.x))) * b.x;
    a.y = (a.y/(1.f+__expf(-a.y))) * b.y;
    a.z = (a.z/(1.f+__expf(-a.z))) * b.z;
    a.w = (a.w/(1.f+__expf(-a.w))) * b.w;
    *(float4*)&g_a1[i] = a;
}

// ---------------- final: out = h + shared + sum_k g2[t*6+k] ----------------
__global__ __launch_bounds__(256) void final_k(float* __restrict__ out) {
    int t = blockIdx.x;
    int c = threadIdx.x * 4;
    float4 a = *(const float4*)&g_h[(size_t)t*DM + c];
    float4 b = *(const float4*)&g_sh[(size_t)t*DM + c];
    a.x += b.x; a.y += b.y; a.z += b.z; a.w += b.w;
    #pragma unroll
    for (int kk = 0; kk < TOPK; kk++) {
        float4 gv = *(const float4*)&g_g2[(size_t)(t*TOPK+kk)*DM + c];
        a.x += gv.x; a.y += gv.y; a.z += gv.z; a.w += gv.w;
    }
    *(float4*)&out[(size_t)t*DM + c] = a;
}

// ---------------- host ----------------
extern "C" void kernel_launch(void* const* d_in, const int* in_sizes, int n_in,
                              void* d_out, int out_size) {
    const float* x   = (const float*)d_in[0];
    const float* fc  = (const float*)d_in[1];
    const float* fs  = (const float*)d_in[2];
    const float* anw = (const float*)d_in[3];
    const float* fnw = (const float*)d_in[4];
    const float* wq  = (const float*)d_in[5];
    const float* wk  = (const float*)d_in[6];
    const float* wv  = (const float*)d_in[7];
    const float* wo  = (const float*)d_in[8];
    const float* qnw = (const float*)d_in[9];
    const float* knw = (const float*)d_in[10];
    const float* gw  = (const float*)d_in[11];
    const float* w1e = (const float*)d_in[12];
    const float* w3e = (const float*)d_in[13];
    const float* w2e = (const float*)d_in[14];
    const float* sw1 = (const float*)d_in[15];
    const float* sw3 = (const float*)d_in[16];
    const float* sw2 = (const float*)d_in[17];
    float* out = (float*)d_out;

    float *hx,*q,*k,*v,*attn,*o,*h,*z,*logits,*a1,*a3,*sh;
    cudaGetSymbolAddress((void**)&hx, g_hx);
    cudaGetSymbolAddress((void**)&q,  g_q);
    cudaGetSymbolAddress((void**)&k,  g_k);
    cudaGetSymbolAddress((void**)&v,  g_v);
    cudaGetSymbolAddress((void**)&attn, g_attn);
    cudaGetSymbolAddress((void**)&o,  g_o);
    cudaGetSymbolAddress((void**)&h,  g_h);
    cudaGetSymbolAddress((void**)&z,  g_z);
    cudaGetSymbolAddress((void**)&logits, g_logits);
    cudaGetSymbolAddress((void**)&a1, g_a1);
    cudaGetSymbolAddress((void**)&a3, g_a3);
    cudaGetSymbolAddress((void**)&sh, g_sh);

    cudaFuncSetAttribute(flash_attn, cudaFuncAttributeMaxDynamicSharedMemorySize, FLASH_SMEM);

    // attention branch
    rmsnorm_k<<<SS, 256>>>(x, anw, hx);
    gemm64<<<dim3(16,16), 256>>>(hx, wq, q, SS, 1024, 1024);
    gemm64<<<dim3(4,16),  256>>>(hx, wk, k, SS, 256, 1024);
    gemm64<<<dim3(4,16),  256>>>(hx, wv, v, SS, 256, 1024);
    qknorm_rope<<<(SS*(NHQ+NKVH)*32)/256, 256>>>(qnw, knw, fc, fs);
    flash_attn<<<dim3(16,16), 256, FLASH_SMEM>>>();
    gemm64<<<dim3(16,16), 256>>>(attn, wo, o, SS, 1024, 1024);
    add_k<<<1024, 256>>>(x);

    // ffn branch
    rmsnorm_k<<<SS, 256>>>(h, fnw, z);
    gemm64<<<dim3(1,16), 256>>>(z, gw, logits, SS, 64, 1024);
    zero_cnt_k<<<1, 64>>>();
    route_k<<<SS, 32>>>();
    moe_gemm1<<<NE*8,  256>>>(w1e, w3e);
    moe_gemm2<<<NE*16, 256>>>(w2e);

    // shared expert
    gemm64<<<dim3(8,16), 256>>>(z, sw1, a1, SS, 512, 1024);
    gemm64<<<dim3(8,16), 256>>>(z, sw3, a3, SS, 512, 1024);
    silu_mul_k<<<(SS*HE)/(256*4), 256>>>();
    gemm64<<<dim3(16,16), 256>>>(a1, sw2, sh, SS, 1024, 512);

    final_k<<<SS, 256>>>(out);
}

// round 4
// speedup vs baseline: 1.1735x; 1.1735x over previous
#include <cuda_runtime.h>
#include <math.h>

#define SS 1024
#define DM 1024
#define NHQ 16
#define NKVH 4
#define HDIM 64
#define NE 64
#define TOPK 6
#define HE 512
#define NPAIR (SS*TOPK)

typedef unsigned long long u64;

// ---------------- packed f32x2 helpers (Blackwell FFMA2 path) ----------------
__device__ __forceinline__ u64 pk2(float x) {
    u64 r; asm("mov.b64 %0,{%1,%1};" : "=l"(r) : "f"(x)); return r;
}
__device__ __forceinline__ void fm2(u64 &d, u64 a, u64 b) {
    asm("fma.rn.f32x2 %0,%1,%2,%0;" : "+l"(d) : "l"(a), "l"(b));
}
__device__ __forceinline__ u64 ad2(u64 a, u64 b) {
    u64 d; asm("add.rn.f32x2 %0,%1,%2;" : "=l"(d) : "l"(a), "l"(b)); return d;
}
__device__ __forceinline__ void up2(float &lo, float &hi, u64 v) {
    asm("mov.b64 {%0,%1},%2;" : "=f"(lo), "=f"(hi) : "l"(v));
}

// ---------------- scratch (device globals; no allocation) ----------------
__device__ float g_hx[SS*DM];
__device__ float g_q[SS*NHQ*HDIM];
__device__ float g_k[SS*NKVH*HDIM];
__device__ float g_v[SS*NKVH*HDIM];
__device__ float g_attn[SS*NHQ*HDIM];
__device__ float g_h[SS*DM];
__device__ float g_z[SS*DM];
__device__ float g_logits[SS*NE];
__device__ float g_pairw[NPAIR];
__device__ int   g_cnt[NE];
__device__ int   g_list[NE*SS];
__device__ float g_gbuf[(size_t)NPAIR*HE];   // per-pair gated hidden
__device__ float g_g2[(size_t)NPAIR*DM];     // per-pair expert output
__device__ float g_a1[SS*HE];
__device__ float g_sh[SS*DM];

// ---------------- rmsnorm: one block per token ----------------
__global__ __launch_bounds__(256) void rmsnorm_k(const float* __restrict__ x,
                                                 const float* __restrict__ w,
                                                 float* __restrict__ out) {
    int t = blockIdx.x;
    int tid = threadIdx.x;
    float4 xv = *(const float4*)&x[(size_t)t*DM + tid*4];
    float ss = xv.x*xv.x + xv.y*xv.y + xv.z*xv.z + xv.w*xv.w;
    #pragma unroll
    for (int off = 16; off; off >>= 1) ss += __shfl_xor_sync(0xffffffffu, ss, off);
    __shared__ float red[8];
    if ((tid & 31) == 0) red[tid >> 5] = ss;
    __syncthreads();
    float tot = 0.f;
    #pragma unroll
    for (int i = 0; i < 8; i++) tot += red[i];
    float r = rsqrtf(tot * (1.0f/DM) + 1e-5f);
    float4 wv = *(const float4*)&w[tid*4];
    float4 ov;
    ov.x = wv.x * (xv.x * r); ov.y = wv.y * (xv.y * r);
    ov.z = wv.z * (xv.z * r); ov.w = wv.w * (xv.w * r);
    *(float4*)&out[(size_t)t*DM + tid*4] = ov;
}

// ============ core FFMA2 tile macros: BM=64, BN=128, BK=16, 256 thr, TM=4, TN=8 ============
// thread map: ty=tid>>4 (row group), tx=tid&15 (col group of 8)
// loader map: amr=tid>>2 (A row), akc=(tid&3)*4 (A k off); bkr=tid>>4, bnc=(tid&15)*8

#define GEMM_K_STEP(As, Bs)                                                        \
    {                                                                              \
        float4 a = *(const float4*)&As[k*68 + ty*4];                               \
        u64 pa0 = pk2(a.x), pa1 = pk2(a.y), pa2 = pk2(a.z), pa3 = pk2(a.w);        \
        ulonglong2 q0 = *(const ulonglong2*)&Bs[k*128 + tx*8];                     \
        ulonglong2 q1 = *(const ulonglong2*)&Bs[k*128 + tx*8 + 4];                 \
        fm2(acc[0][0],pa0,q0.x); fm2(acc[0][1],pa0,q0.y);                          \
        fm2(acc[0][2],pa0,q1.x); fm2(acc[0][3],pa0,q1.y);                          \
        fm2(acc[1][0],pa1,q0.x); fm2(acc[1][1],pa1,q0.y);                          \
        fm2(acc[1][2],pa1,q1.x); fm2(acc[1][3],pa1,q1.y);                          \
        fm2(acc[2][0],pa2,q0.x); fm2(acc[2][1],pa2,q0.y);                          \
        fm2(acc[2][2],pa2,q1.x); fm2(acc[2][3],pa2,q1.y);                          \
        fm2(acc[3][0],pa3,q0.x); fm2(acc[3][1],pa3,q0.y);                          \
        fm2(acc[3][2],pa3,q1.x); fm2(acc[3][3],pa3,q1.y);                          \
    }

#define DUAL_K_STEP(As, B1s, B2s)                                                  \
    {                                                                              \
        float4 a = *(const float4*)&As[k*68 + ty*4];                               \
        u64 pa0 = pk2(a.x), pa1 = pk2(a.y), pa2 = pk2(a.z), pa3 = pk2(a.w);        \
        ulonglong2 r1 = *(const ulonglong2*)&B1s[k*64 + tx*4];                     \
        ulonglong2 r2 = *(const ulonglong2*)&B2s[k*64 + tx*4];                     \
        fm2(acc1[0][0],pa0,r1.x); fm2(acc1[0][1],pa0,r1.y);                        \
        fm2(acc1[1][0],pa1,r1.x); fm2(acc1[1][1],pa1,r1.y);                        \
        fm2(acc1[2][0],pa2,r1.x); fm2(acc1[2][1],pa2,r1.y);                        \
        fm2(acc1[3][0],pa3,r1.x); fm2(acc1[3][1],pa3,r1.y);                        \
        fm2(acc3[0][0],pa0,r2.x); fm2(acc3[0][1],pa0,r2.y);                        \
        fm2(acc3[1][0],pa1,r2.x); fm2(acc3[1][1],pa1,r2.y);                        \
        fm2(acc3[2][0],pa2,r2.x); fm2(acc3[2][1],pa2,r2.y);                        \
        fm2(acc3[3][0],pa3,r2.x); fm2(acc3[3][1],pa3,r2.y);                        \
    }

// ---------------- fused QKV GEMM: A=hx (1024x1024); blocks pick wq/wk/wv ----------------
__global__ __launch_bounds__(256) void qkv_gemm(const float* __restrict__ A,
                                                const float* __restrict__ wq,
                                                const float* __restrict__ wk,
                                                const float* __restrict__ wv) {
    __shared__ float As[16*68];
    __shared__ float Bs[16*128];
    int bn = blockIdx.x, m0 = blockIdx.y * 64;
    const float* B; float* C; int ldb; int col;
    if (bn < 8)       { B = wq; C = g_q; ldb = 1024; col = bn * 128; }
    else if (bn < 10) { B = wk; C = g_k; ldb = 256;  col = (bn - 8) * 128; }
    else              { B = wv; C = g_v; ldb = 256;  col = (bn - 10) * 128; }
    int tid = threadIdx.x, ty = tid >> 4, tx = tid & 15;
    int amr = tid >> 2, akc = (tid & 3) * 4;
    int bkr = tid >> 4, bnc = (tid & 15) * 8;
    const float* Arow = &A[(size_t)(m0 + amr) * DM];
    u64 acc[4][4] = {};
    for (int k0 = 0; k0 < DM; k0 += 16) {
        float4 av = *(const float4*)&Arow[k0 + akc];
        const float* bp = &B[(size_t)(k0 + bkr) * ldb + col + bnc];
        float4 b0 = *(const float4*)bp;
        float4 b1 = *(const float4*)(bp + 4);
        As[(akc+0)*68 + amr] = av.x; As[(akc+1)*68 + amr] = av.y;
        As[(akc+2)*68 + amr] = av.z; As[(akc+3)*68 + amr] = av.w;
        *(float4*)&Bs[bkr*128 + bnc]     = b0;
        *(float4*)&Bs[bkr*128 + bnc + 4] = b1;
        __syncthreads();
        #pragma unroll
        for (int k = 0; k < 16; k++) GEMM_K_STEP(As, Bs)
        __syncthreads();
    }
    #pragma unroll
    for (int i = 0; i < 4; i++) {
        float* crow = &C[(size_t)(m0 + ty*4 + i) * ldb + col + tx*8];
        #pragma unroll
        for (int j = 0; j < 4; j++) *(float2*)&crow[2*j] = *(float2*)&acc[i][j];
    }
}

// ---------------- generic GEMM + optional residual: C = A@B (+res) ----------------
__global__ __launch_bounds__(256) void sgemm_res(const float* __restrict__ A,
                                                 const float* __restrict__ B,
                                                 float* __restrict__ C,
                                                 const float* __restrict__ res,
                                                 int N, int K) {
    __shared__ float As[16*68];
    __shared__ float Bs[16*128];
    int n0 = blockIdx.x * 128, m0 = blockIdx.y * 64;
    int tid = threadIdx.x, ty = tid >> 4, tx = tid & 15;
    int amr = tid >> 2, akc = (tid & 3) * 4;
    int bkr = tid >> 4, bnc = (tid & 15) * 8;
    const float* Arow = &A[(size_t)(m0 + amr) * K];
    u64 acc[4][4] = {};
    for (int k0 = 0; k0 < K; k0 += 16) {
        float4 av = *(const float4*)&Arow[k0 + akc];
        const float* bp = &B[(size_t)(k0 + bkr) * N + n0 + bnc];
        float4 b0 = *(const float4*)bp;
        float4 b1 = *(const float4*)(bp + 4);
        As[(akc+0)*68 + amr] = av.x; As[(akc+1)*68 + amr] = av.y;
        As[(akc+2)*68 + amr] = av.z; As[(akc+3)*68 + amr] = av.w;
        *(float4*)&Bs[bkr*128 + bnc]     = b0;
        *(float4*)&Bs[bkr*128 + bnc + 4] = b1;
        __syncthreads();
        #pragma unroll
        for (int k = 0; k < 16; k++) GEMM_K_STEP(As, Bs)
        __syncthreads();
    }
    #pragma unroll
    for (int i = 0; i < 4; i++) {
        size_t ridx = (size_t)(m0 + ty*4 + i) * N + n0 + tx*8;
        if (res) {
            #pragma unroll
            for (int j = 0; j < 4; j++) {
                u64 rv = *(const u64*)&res[ridx + 2*j];
                u64 s = ad2(acc[i][j], rv);
                *(float2*)&C[ridx + 2*j] = *(float2*)&s;
            }
        } else {
            #pragma unroll
            for (int j = 0; j < 4; j++) *(float2*)&C[ridx + 2*j] = *(float2*)&acc[i][j];
        }
    }
}

// ---------------- shared expert dual GEMM: g_a1 = silu(z@sw1)*(z@sw3) ----------------
__global__ __launch_bounds__(256) void dual_shared(const float* __restrict__ A,
                                                   const float* __restrict__ B1,
                                                   const float* __restrict__ B2) {
    __shared__ float As[16*68];
    __shared__ float B1s[16*64];
    __shared__ float B2s[16*64];
    int n0 = blockIdx.x * 64, m0 = blockIdx.y * 64;
    int tid = threadIdx.x, ty = tid >> 4, tx = tid & 15;
    int amr = tid >> 2, akc = (tid & 3) * 4;
    int bkr = tid >> 4, bnc = (tid & 15) * 4;
    const float* Arow = &A[(size_t)(m0 + amr) * DM];
    u64 acc1[4][2] = {}; u64 acc3[4][2] = {};
    for (int k0 = 0; k0 < DM; k0 += 16) {
        float4 av = *(const float4*)&Arow[k0 + akc];
        float4 b1 = *(const float4*)&B1[(size_t)(k0 + bkr) * HE + n0 + bnc];
        float4 b2 = *(const float4*)&B2[(size_t)(k0 + bkr) * HE + n0 + bnc];
        As[(akc+0)*68 + amr] = av.x; As[(akc+1)*68 + amr] = av.y;
        As[(akc+2)*68 + amr] = av.z; As[(akc+3)*68 + amr] = av.w;
        *(float4*)&B1s[bkr*64 + bnc] = b1;
        *(float4*)&B2s[bkr*64 + bnc] = b2;
        __syncthreads();
        #pragma unroll
        for (int k = 0; k < 16; k++) DUAL_K_STEP(As, B1s, B2s)
        __syncthreads();
    }
    #pragma unroll
    for (int i = 0; i < 4; i++) {
        float* crow = &g_a1[(size_t)(m0 + ty*4 + i) * HE + n0 + tx*4];
        #pragma unroll
        for (int p = 0; p < 2; p++) {
            float x0,x1,y0,y1;
            up2(x0,x1,acc1[i][p]); up2(y0,y1,acc3[i][p]);
            float2 o;
            o.x = (x0/(1.f+__expf(-x0))) * y0;
            o.y = (x1/(1.f+__expf(-x1))) * y1;
            *(float2*)&crow[2*p] = o;
        }
    }
}

// ---------------- q/k rmsnorm + rope: one warp per (token, head) ----------------
__global__ __launch_bounds__(256) void qknorm_rope(const float* __restrict__ qw,
                                                   const float* __restrict__ kw,
                                                   const float* __restrict__ cosb,
                                                   const float* __restrict__ sinb) {
    int gw = (blockIdx.x * blockDim.x + threadIdx.x) >> 5;
    int lane = threadIdx.x & 31;
    if (gw >= SS * (NHQ + NKVH)) return;
    int t = gw / (NHQ + NKVH);
    int hh = gw % (NHQ + NKVH);
    float* base;
    const float* w;
    if (hh < NHQ) { base = &g_q[(size_t)t*(NHQ*HDIM) + hh*HDIM]; w = qw; }
    else          { base = &g_k[(size_t)t*(NKVH*HDIM) + (hh-NHQ)*HDIM]; w = kw; }
    int d0 = lane * 2;
    float v0 = base[d0], v1 = base[d0+1];
    float ss = v0*v0 + v1*v1;
    #pragma unroll
    for (int off = 16; off; off >>= 1) ss += __shfl_xor_sync(0xffffffffu, ss, off);
    float r = rsqrtf(ss * (1.0f/HDIM) + 1e-5f);
    float n0 = v0 * r * w[d0];
    float n1 = v1 * r * w[d0+1];
    float c = cosb[t*(HDIM/2) + lane];
    float s = sinb[t*(HDIM/2) + lane];
    base[d0]   = n0*c - n1*s;
    base[d0+1] = n0*s + n1*c;
}

// ---------------- flash attention, fp32, causal, GQA 4:1 (unchanged, proven) ----------------
#define FLASH_SMEM (4*64*65*4)
__global__ __launch_bounds__(256) void flash_attn() {
    extern __shared__ float sm[];
    float* Qs = sm;
    float* Ks = sm + 64*65;
    float* Vs = sm + 2*64*65;
    float* Ps = sm + 3*64*65;
    int qt = blockIdx.x, h = blockIdx.y;
    int kvh = h >> 2;
    int q0 = qt * 64;
    int tid = threadIdx.x;
    int tx = tid & 15, ty = tid >> 4;
    {
        int r = tid >> 2, c = (tid & 3) * 16;
        const float* src = &g_q[(size_t)(q0 + r)*(NHQ*HDIM) + h*HDIM + c];
        #pragma unroll
        for (int i = 0; i < 16; i += 4) {
            float4 vq = *(const float4*)(src + i);
            Qs[r*65+c+i]   = vq.x; Qs[r*65+c+i+1] = vq.y;
            Qs[r*65+c+i+2] = vq.z; Qs[r*65+c+i+3] = vq.w;
        }
    }
    float O[4][4] = {};
    float m_i[4] = {-1e30f,-1e30f,-1e30f,-1e30f};
    float l_i[4] = {};
    __syncthreads();
    for (int kt = 0; kt <= qt; kt++) {
        int k0 = kt * 64;
        {
            int r = tid >> 2, c = (tid & 3) * 16;
            const float* ksrc = &g_k[(size_t)(k0 + r)*(NKVH*HDIM) + kvh*HDIM + c];
            const float* vsrc = &g_v[(size_t)(k0 + r)*(NKVH*HDIM) + kvh*HDIM + c];
            #pragma unroll
            for (int i = 0; i < 16; i += 4) {
                float4 a = *(const float4*)(ksrc + i);
                float4 b = *(const float4*)(vsrc + i);
                Ks[r*65+c+i]=a.x; Ks[r*65+c+i+1]=a.y; Ks[r*65+c+i+2]=a.z; Ks[r*65+c+i+3]=a.w;
                Vs[r*65+c+i]=b.x; Vs[r*65+c+i+1]=b.y; Vs[r*65+c+i+2]=b.z; Vs[r*65+c+i+3]=b.w;
            }
        }
        __syncthreads();
        float s[4][4] = {};
        #pragma unroll 8
        for (int d = 0; d < 64; d++) {
            float qv[4], kv[4];
            #pragma unroll
            for (int i = 0; i < 4; i++) qv[i] = Qs[(ty*4+i)*65 + d];
            #pragma unroll
            for (int j = 0; j < 4; j++) kv[j] = Ks[(tx*4+j)*65 + d];
            #pragma unroll
            for (int i = 0; i < 4; i++)
                #pragma unroll
                for (int j = 0; j < 4; j++)
                    s[i][j] += qv[i]*kv[j];
        }
        const float sc = 0.125f;
        if (kt == qt) {
            #pragma unroll
            for (int i = 0; i < 4; i++)
                #pragma unroll
                for (int j = 0; j < 4; j++)
                    s[i][j] = (tx*4+j <= ty*4+i) ? s[i][j]*sc : -1e30f;
        } else {
            #pragma unroll
            for (int i = 0; i < 4; i++)
                #pragma unroll
                for (int j = 0; j < 4; j++)
                    s[i][j] *= sc;
        }
        #pragma unroll
        for (int i = 0; i < 4; i++) {
            float mx = fmaxf(fmaxf(s[i][0],s[i][1]), fmaxf(s[i][2],s[i][3]));
            mx = fmaxf(mx, __shfl_xor_sync(0xffffffffu, mx, 1));
            mx = fmaxf(mx, __shfl_xor_sync(0xffffffffu, mx, 2));
            mx = fmaxf(mx, __shfl_xor_sync(0xffffffffu, mx, 4));
            mx = fmaxf(mx, __shfl_xor_sync(0xffffffffu, mx, 8));
            float mn = fmaxf(m_i[i], mx);
            float scale = __expf(m_i[i] - mn);
            float rs = 0.f;
            #pragma unroll
            for (int j = 0; j < 4; j++) { float p = __expf(s[i][j]-mn); s[i][j]=p; rs += p; }
            rs += __shfl_xor_sync(0xffffffffu, rs, 1);
            rs += __shfl_xor_sync(0xffffffffu, rs, 2);
            rs += __shfl_xor_sync(0xffffffffu, rs, 4);
            rs += __shfl_xor_sync(0xffffffffu, rs, 8);
            l_i[i] = l_i[i]*scale + rs;
            m_i[i] = mn;
            #pragma unroll
            for (int j = 0; j < 4; j++) {
                O[i][j] *= scale;
                Ps[(ty*4+i)*65 + tx*4+j] = s[i][j];
            }
        }
        __syncthreads();
        #pragma unroll 4
        for (int jj = 0; jj < 64; jj++) {
            float pv[4], vv[4];
            #pragma unroll
            for (int i = 0; i < 4; i++) pv[i] = Ps[(ty*4+i)*65 + jj];
            #pragma unroll
            for (int j = 0; j < 4; j++) vv[j] = Vs[jj*65 + tx*4+j];
            #pragma unroll
            for (int i = 0; i < 4; i++)
                #pragma unroll
                for (int j = 0; j < 4; j++)
                    O[i][j] += pv[i]*vv[j];
        }
        __syncthreads();
    }
    #pragma unroll
    for (int i = 0; i < 4; i++) {
        float inv = 1.f / l_i[i];
        #pragma unroll
        for (int j = 0; j < 4; j++)
            g_attn[(size_t)(q0+ty*4+i)*(NHQ*HDIM) + h*HDIM + tx*4+j] = O[i][j]*inv;
    }
}

// ---------------- gate GEMM (small N=64): old 64x64 tile kernel ----------------
__global__ __launch_bounds__(256) void gemm64(const float* __restrict__ A,
                                              const float* __restrict__ B,
                                              float* __restrict__ C,
                                              int M, int N, int K) {
    __shared__ float As[16][64];
    __shared__ float Bs[16][64];
    int tid = threadIdx.x;
    int tx = tid & 15, ty = tid >> 4;
    int m0 = blockIdx.y * 64, n0 = blockIdx.x * 64;
    int ar = tid >> 2;
    int ac = (tid & 3) * 4;
    int br = tid >> 4;
    int bc = (tid & 15) * 4;
    float acc[4][4] = {};
    for (int k0 = 0; k0 < K; k0 += 16) {
        float4 av = *(const float4*)&A[(size_t)(m0 + ar)*K + k0 + ac];
        float4 bv = *(const float4*)&B[(size_t)(k0 + br)*N + n0 + bc];
        As[ac+0][ar] = av.x; As[ac+1][ar] = av.y;
        As[ac+2][ar] = av.z; As[ac+3][ar] = av.w;
        *(float4*)&Bs[br][bc] = bv;
        __syncthreads();
        #pragma unroll
        for (int k = 0; k < 16; k++) {
            float4 a = *(const float4*)&As[k][ty*4];
            float4 b = *(const float4*)&Bs[k][tx*4];
            float aa[4] = {a.x,a.y,a.z,a.w};
            float bb[4] = {b.x,b.y,b.z,b.w};
            #pragma unroll
            for (int i = 0; i < 4; i++)
                #pragma unroll
                for (int j = 0; j < 4; j++)
                    acc[i][j] += aa[i]*bb[j];
        }
        __syncthreads();
    }
    #pragma unroll
    for (int i = 0; i < 4; i++) {
        float4 ov = make_float4(acc[i][0],acc[i][1],acc[i][2],acc[i][3]);
        *(float4*)&C[(size_t)(m0 + ty*4 + i)*N + n0 + tx*4] = ov;
    }
}

// ---------------- routing: top-6 + expert list build; one warp/token ----------------
__global__ void zero_cnt_k() { if (threadIdx.x < NE) g_cnt[threadIdx.x] = 0; }

__global__ void route_k() {
    int t = blockIdx.x;
    int lane = threadIdx.x;
    float v0 = g_logits[t*NE + lane];
    float v1 = g_logits[t*NE + 32 + lane];
    float selv[TOPK]; int seli[TOPK];
    #pragma unroll
    for (int it = 0; it < TOPK; it++) {
        float best = (v0 >= v1) ? v0 : v1;
        int   bi   = (v0 >= v1) ? lane : lane + 32;
        #pragma unroll
        for (int off = 16; off; off >>= 1) {
            float ov = __shfl_xor_sync(0xffffffffu, best, off);
            int   oi = __shfl_xor_sync(0xffffffffu, bi, off);
            if (ov > best || (ov == best && oi < bi)) { best = ov; bi = oi; }
        }
        selv[it] = best; seli[it] = bi;
        if (bi == lane)      v0 = -1e30f;
        if (bi == lane + 32) v1 = -1e30f;
    }
    if (lane < TOPK) {
        float sum = 0.f;
        #pragma unroll
        for (int i = 0; i < TOPK; i++) sum += __expf(selv[i] - selv[0]);
        float w = __expf(selv[lane] - selv[0]) / sum;
        int e = seli[lane];
        int pos = atomicAdd(&g_cnt[e], 1);
        g_list[e*SS + pos] = t*TOPK + lane;
        g_pairw[t*TOPK + lane] = w;
    }
}

// ---------------- MoE GEMM1 (grouped dual): g_gbuf[p] = silu(z@W1_e)*(z@W3_e)*w_p ----------------
// grid.x = NE*8: e = bid>>3, n0 = (bid&7)*64 over HE. BM=64 m-loop.
__global__ __launch_bounds__(256) void moe_gemm1(const float* __restrict__ w1e,
                                                 const float* __restrict__ w3e) {
    int e  = blockIdx.x >> 3;
    int n0 = (blockIdx.x & 7) * 64;
    int n = g_cnt[e];
    if (n == 0) return;
    const int* lst = &g_list[e*SS];
    const float* W1 = w1e + (size_t)e * DM * HE;
    const float* W3 = w3e + (size_t)e * DM * HE;
    __shared__ float As[16*68];
    __shared__ float B1s[16*64];
    __shared__ float B2s[16*64];
    __shared__ int s_p[64];
    int tid = threadIdx.x, ty = tid >> 4, tx = tid & 15;
    int amr = tid >> 2, akc = (tid & 3) * 4;
    int bkr = tid >> 4, bnc = (tid & 15) * 4;
    for (int m0 = 0; m0 < n; m0 += 64) {
        __syncthreads();
        if (tid < 64) s_p[tid] = (m0 + tid < n) ? lst[m0 + tid] : -1;
        __syncthreads();
        int pz = s_p[amr];
        const float* Arow = &g_z[(size_t)(pz < 0 ? 0 : pz / TOPK) * DM];
        u64 acc1[4][2] = {}; u64 acc3[4][2] = {};
        for (int k0 = 0; k0 < DM; k0 += 16) {
            float4 av = *(const float4*)&Arow[k0 + akc];
            float4 b1 = *(const float4*)&W1[(size_t)(k0 + bkr) * HE + n0 + bnc];
            float4 b2 = *(const float4*)&W3[(size_t)(k0 + bkr) * HE + n0 + bnc];
            As[(akc+0)*68 + amr] = av.x; As[(akc+1)*68 + amr] = av.y;
            As[(akc+2)*68 + amr] = av.z; As[(akc+3)*68 + amr] = av.w;
            *(float4*)&B1s[bkr*64 + bnc] = b1;
            *(float4*)&B2s[bkr*64 + bnc] = b2;
            __syncthreads();
            #pragma unroll
            for (int k = 0; k < 16; k++) DUAL_K_STEP(As, B1s, B2s)
            __syncthreads();
        }
        #pragma unroll
        for (int i = 0; i < 4; i++) {
            int pr = s_p[ty*4 + i];
            if (pr >= 0) {
                float w = g_pairw[pr];
                float* crow = &g_gbuf[(size_t)pr * HE + n0 + tx*4];
                #pragma unroll
                for (int p = 0; p < 2; p++) {
                    float x0,x1,y0,y1;
                    up2(x0,x1,acc1[i][p]); up2(y0,y1,acc3[i][p]);
                    float2 o;
                    o.x = (x0/(1.f+__expf(-x0))) * y0 * w;
                    o.y = (x1/(1.f+__expf(-x1))) * y1 * w;
                    *(float2*)&crow[2*p] = o;
                }
            }
        }
    }
}

// ---------------- MoE GEMM2 (grouped): g_g2[p] = g_gbuf[p] @ W2_e ----------------
// grid.x = NE*8: e = bid>>3, n0 = (bid&7)*128 over DM. BM=64 m-loop, K=HE.
__global__ __launch_bounds__(256) void moe_gemm2(const float* __restrict__ w2e) {
    int e  = blockIdx.x >> 3;
    int n0 = (blockIdx.x & 7) * 128;
    int n = g_cnt[e];
    if (n == 0) return;
    const int* lst = &g_list[e*SS];
    const float* W2 = w2e + (size_t)e * HE * DM;
    __shared__ float As[16*68];
    __shared__ float Bs[16*128];
    __shared__ int s_p[64];
    int tid = threadIdx.x, ty = tid >> 4, tx = tid & 15;
    int amr = tid >> 2, akc = (tid & 3) * 4;
    int bkr = tid >> 4, bnc = (tid & 15) * 8;
    for (int m0 = 0; m0 < n; m0 += 64) {
        __syncthreads();
        if (tid < 64) s_p[tid] = (m0 + tid < n) ? lst[m0 + tid] : -1;
        __syncthreads();
        int pz = s_p[amr];
        const float* Arow = &g_gbuf[(size_t)(pz < 0 ? 0 : pz) * HE];
        u64 acc[4][4] = {};
        for (int k0 = 0; k0 < HE; k0 += 16) {
            float4 av = *(const float4*)&Arow[k0 + akc];
            const float* bp = &W2[(size_t)(k0 + bkr) * DM + n0 + bnc];
            float4 b0 = *(const float4*)bp;
            float4 b1 = *(const float4*)(bp + 4);
            As[(akc+0)*68 + amr] = av.x; As[(akc+1)*68 + amr] = av.y;
            As[(akc+2)*68 + amr] = av.z; As[(akc+3)*68 + amr] = av.w;
            *(float4*)&Bs[bkr*128 + bnc]     = b0;
            *(float4*)&Bs[bkr*128 + bnc + 4] = b1;
            __syncthreads();
            #pragma unroll
            for (int k = 0; k < 16; k++) GEMM_K_STEP(As, Bs)
            __syncthreads();
        }
        #pragma unroll
        for (int i = 0; i < 4; i++) {
            int pr = s_p[ty*4 + i];
            if (pr >= 0) {
                float* crow = &g_g2[(size_t)pr * DM + n0 + tx*8];
                #pragma unroll
                for (int j = 0; j < 4; j++) *(float2*)&crow[2*j] = *(float2*)&acc[i][j];
            }
        }
    }
}

// ---------------- final: out = h + shared + sum_k g2[t*6+k] ----------------
__global__ __launch_bounds__(256) void final_k(float* __restrict__ out) {
    int t = blockIdx.x;
    int c = threadIdx.x * 4;
    float4 a = *(const float4*)&g_h[(size_t)t*DM + c];
    float4 b = *(const float4*)&g_sh[(size_t)t*DM + c];
    a.x += b.x; a.y += b.y; a.z += b.z; a.w += b.w;
    #pragma unroll
    for (int kk = 0; kk < TOPK; kk++) {
        float4 gv = *(const float4*)&g_g2[(size_t)(t*TOPK+kk)*DM + c];
        a.x += gv.x; a.y += gv.y; a.z += gv.z; a.w += gv.w;
    }
    *(float4*)&out[(size_t)t*DM + c] = a;
}

// ---------------- host ----------------
extern "C" void kernel_launch(void* const* d_in, const int* in_sizes, int n_in,
                              void* d_out, int out_size) {
    const float* x   = (const float*)d_in[0];
    const float* fc  = (const float*)d_in[1];
    const float* fs  = (const float*)d_in[2];
    const float* anw = (const float*)d_in[3];
    const float* fnw = (const float*)d_in[4];
    const float* wq  = (const float*)d_in[5];
    const float* wk  = (const float*)d_in[6];
    const float* wv  = (const float*)d_in[7];
    const float* wo  = (const float*)d_in[8];
    const float* qnw = (const float*)d_in[9];
    const float* knw = (const float*)d_in[10];
    const float* gw  = (const float*)d_in[11];
    const float* w1e = (const float*)d_in[12];
    const float* w3e = (const float*)d_in[13];
    const float* w2e = (const float*)d_in[14];
    const float* sw1 = (const float*)d_in[15];
    const float* sw3 = (const float*)d_in[16];
    const float* sw2 = (const float*)d_in[17];
    float* out = (float*)d_out;

    float *hx,*attn,*h,*z,*logits,*a1,*sh;
    cudaGetSymbolAddress((void**)&hx, g_hx);
    cudaGetSymbolAddress((void**)&attn, g_attn);
    cudaGetSymbolAddress((void**)&h,  g_h);
    cudaGetSymbolAddress((void**)&z,  g_z);
    cudaGetSymbolAddress((void**)&logits, g_logits);
    cudaGetSymbolAddress((void**)&a1, g_a1);
    cudaGetSymbolAddress((void**)&sh, g_sh);

    cudaFuncSetAttribute(flash_attn, cudaFuncAttributeMaxDynamicSharedMemorySize, FLASH_SMEM);

    // attention branch
    rmsnorm_k<<<SS, 256>>>(x, anw, hx);
    qkv_gemm<<<dim3(12, 16), 256>>>(hx, wq, wk, wv);
    qknorm_rope<<<(SS*(NHQ+NKVH)*32)/256, 256>>>(qnw, knw, fc, fs);
    flash_attn<<<dim3(16,16), 256, FLASH_SMEM>>>();
    sgemm_res<<<dim3(8, 16), 256>>>(attn, wo, h, x, 1024, 1024);   // h = attn@wo + x

    // ffn branch
    rmsnorm_k<<<SS, 256>>>(h, fnw, z);
    gemm64<<<dim3(1, 16), 256>>>(z, gw, logits, SS, NE, DM);
    zero_cnt_k<<<1, 64>>>();
    route_k<<<SS, 32>>>();
    moe_gemm1<<<NE*8, 256>>>(w1e, w3e);
    moe_gemm2<<<NE*8, 256>>>(w2e);

    // shared expert (silu*mul fused into dual GEMM epilogue)
    dual_shared<<<dim3(8, 16), 256>>>(z, sw1, sw3);
    sgemm_res<<<dim3(8, 16), 256>>>(a1, sw2, sh, nullptr, 1024, 512);

    final_k<<<SS, 256>>>(out);
}

// round 5
// speedup vs baseline: 1.2344x; 1.0519x over previous
#include <cuda_runtime.h>
#include <math.h>

#define SS 1024
#define DM 1024
#define NHQ 16
#define NKVH 4
#define HDIM 64
#define NE 64
#define TOPK 6
#define HE 512
#define NPAIR (SS*TOPK)

typedef unsigned long long u64;

// ---------------- packed f32x2 helpers (Blackwell FFMA2 path) ----------------
__device__ __forceinline__ u64 pk2(float x) {
    u64 r; asm("mov.b64 %0,{%1,%1};" : "=l"(r) : "f"(x)); return r;
}
__device__ __forceinline__ void fm2(u64 &d, u64 a, u64 b) {
    asm("fma.rn.f32x2 %0,%1,%2,%0;" : "+l"(d) : "l"(a), "l"(b));
}
__device__ __forceinline__ u64 ad2(u64 a, u64 b) {
    u64 d; asm("add.rn.f32x2 %0,%1,%2;" : "=l"(d) : "l"(a), "l"(b)); return d;
}
__device__ __forceinline__ void up2(float &lo, float &hi, u64 v) {
    asm("mov.b64 {%0,%1},%2;" : "=f"(lo), "=f"(hi) : "l"(v));
}

// ---------------- scratch (device globals; no allocation) ----------------
__device__ float g_hx[SS*DM];
__device__ float g_q[SS*NHQ*HDIM];
__device__ float g_k[SS*NKVH*HDIM];
__device__ float g_v[SS*NKVH*HDIM];
__device__ float g_attn[SS*NHQ*HDIM];
__device__ float g_h[SS*DM];
__device__ float g_z[SS*DM];
__device__ float g_logits[SS*NE];
__device__ float g_pairw[NPAIR];
__device__ int   g_cnt[NE];
__device__ int   g_list[NE*SS];
__device__ float g_gbuf[(size_t)NPAIR*HE];
__device__ float g_g2[(size_t)NPAIR*DM];
__device__ float g_a1[SS*HE];
__device__ float g_sh[SS*DM];

// ---------------- rmsnorm: one block per token ----------------
__global__ __launch_bounds__(256) void rmsnorm_k(const float* __restrict__ x,
                                                 const float* __restrict__ w,
                                                 float* __restrict__ out) {
    int t = blockIdx.x;
    int tid = threadIdx.x;
    float4 xv = *(const float4*)&x[(size_t)t*DM + tid*4];
    float ss = xv.x*xv.x + xv.y*xv.y + xv.z*xv.z + xv.w*xv.w;
    #pragma unroll
    for (int off = 16; off; off >>= 1) ss += __shfl_xor_sync(0xffffffffu, ss, off);
    __shared__ float red[8];
    if ((tid & 31) == 0) red[tid >> 5] = ss;
    __syncthreads();
    float tot = 0.f;
    #pragma unroll
    for (int i = 0; i < 8; i++) tot += red[i];
    float r = rsqrtf(tot * (1.0f/DM) + 1e-5f);
    float4 wv = *(const float4*)&w[tid*4];
    float4 ov;
    ov.x = wv.x * (xv.x * r); ov.y = wv.y * (xv.y * r);
    ov.z = wv.z * (xv.z * r); ov.w = wv.w * (xv.w * r);
    *(float4*)&out[(size_t)t*DM + tid*4] = ov;
}

// ============ FFMA2 tile: BM=64, BN=128, BK=16, 256 thr, TM=4, TN=8 ============
// thread map: ty=tid>>4 (row group), tx=tid&15 (col group of 8)
// loader map: amr=tid>>2 (A row), akc=(tid&3)*4; bkr=tid>>4, bnc=(tid&15)*8

#define GEMM_K_STEP(Ap, Bp)                                                        \
    {                                                                              \
        float4 a = *(const float4*)&(Ap)[k*68 + ty*4];                             \
        u64 pa0 = pk2(a.x), pa1 = pk2(a.y), pa2 = pk2(a.z), pa3 = pk2(a.w);        \
        ulonglong2 q0 = *(const ulonglong2*)&(Bp)[k*128 + tx*8];                   \
        ulonglong2 q1 = *(const ulonglong2*)&(Bp)[k*128 + tx*8 + 4];               \
        fm2(acc[0][0],pa0,q0.x); fm2(acc[0][1],pa0,q0.y);                          \
        fm2(acc[0][2],pa0,q1.x); fm2(acc[0][3],pa0,q1.y);                          \
        fm2(acc[1][0],pa1,q0.x); fm2(acc[1][1],pa1,q0.y);                          \
        fm2(acc[1][2],pa1,q1.x); fm2(acc[1][3],pa1,q1.y);                          \
        fm2(acc[2][0],pa2,q0.x); fm2(acc[2][1],pa2,q0.y);                          \
        fm2(acc[2][2],pa2,q1.x); fm2(acc[2][3],pa2,q1.y);                          \
        fm2(acc[3][0],pa3,q0.x); fm2(acc[3][1],pa3,q0.y);                          \
        fm2(acc[3][2],pa3,q1.x); fm2(acc[3][3],pa3,q1.y);                          \
    }

#define DUAL_K_STEP(Ap, B1p, B2p)                                                  \
    {                                                                              \
        float4 a = *(const float4*)&(Ap)[k*68 + ty*4];                             \
        u64 pa0 = pk2(a.x), pa1 = pk2(a.y), pa2 = pk2(a.z), pa3 = pk2(a.w);        \
        ulonglong2 r1 = *(const ulonglong2*)&(B1p)[k*64 + tx*4];                   \
        ulonglong2 r2 = *(const ulonglong2*)&(B2p)[k*64 + tx*4];                   \
        fm2(acc1[0][0],pa0,r1.x); fm2(acc1[0][1],pa0,r1.y);                        \
        fm2(acc1[1][0],pa1,r1.x); fm2(acc1[1][1],pa1,r1.y);                        \
        fm2(acc1[2][0],pa2,r1.x); fm2(acc1[2][1],pa2,r1.y);                        \
        fm2(acc1[3][0],pa3,r1.x); fm2(acc1[3][1],pa3,r1.y);                        \
        fm2(acc3[0][0],pa0,r2.x); fm2(acc3[0][1],pa0,r2.y);                        \
        fm2(acc3[1][0],pa1,r2.x); fm2(acc3[1][1],pa1,r2.y);                        \
        fm2(acc3[2][0],pa2,r2.x); fm2(acc3[2][1],pa3,r2.y);                        \
        fm2(acc3[3][0],pa3,r2.x); fm2(acc3[3][1],pa3,r2.y);                        \
    }

// store helpers for the double-buffered loaders
#define STORE_A(Ap, av)                                                            \
    { (Ap)[(akc+0)*68 + amr] = (av).x; (Ap)[(akc+1)*68 + amr] = (av).y;            \
      (Ap)[(akc+2)*68 + amr] = (av).z; (Ap)[(akc+3)*68 + amr] = (av).w; }

// ---------------- fused QKV GEMM (double-buffered) ----------------
__global__ __launch_bounds__(256) void qkv_gemm(const float* __restrict__ A,
                                                const float* __restrict__ wq,
                                                const float* __restrict__ wk,
                                                const float* __restrict__ wv) {
    __shared__ float As[2][16*68];
    __shared__ float Bs[2][16*128];
    int bn = blockIdx.x, m0 = blockIdx.y * 64;
    const float* B; float* C; int ldb; int col;
    if (bn < 8)       { B = wq; C = g_q; ldb = 1024; col = bn * 128; }
    else if (bn < 10) { B = wk; C = g_k; ldb = 256;  col = (bn - 8) * 128; }
    else              { B = wv; C = g_v; ldb = 256;  col = (bn - 10) * 128; }
    int tid = threadIdx.x, ty = tid >> 4, tx = tid & 15;
    int amr = tid >> 2, akc = (tid & 3) * 4;
    int bkr = tid >> 4, bnc = (tid & 15) * 8;
    const float* Arow = &A[(size_t)(m0 + amr) * DM];
    const float* Bp0 = &B[(size_t)bkr * ldb + col + bnc];
    u64 acc[4][4] = {};
    {
        float4 av = *(const float4*)&Arow[akc];
        float4 b0 = *(const float4*)Bp0;
        float4 b1 = *(const float4*)(Bp0 + 4);
        STORE_A(As[0], av);
        *(float4*)&Bs[0][bkr*128 + bnc]     = b0;
        *(float4*)&Bs[0][bkr*128 + bnc + 4] = b1;
    }
    __syncthreads();
    int buf = 0;
    for (int k0 = 16; k0 <= DM; k0 += 16) {
        float4 nav, nb0, nb1;
        bool more = (k0 < DM);
        if (more) {
            nav = *(const float4*)&Arow[k0 + akc];
            const float* bp = Bp0 + (size_t)k0 * ldb;
            nb0 = *(const float4*)bp;
            nb1 = *(const float4*)(bp + 4);
        }
        #pragma unroll
        for (int k = 0; k < 16; k++) GEMM_K_STEP(As[buf], Bs[buf])
        if (more) {
            STORE_A(As[buf^1], nav);
            *(float4*)&Bs[buf^1][bkr*128 + bnc]     = nb0;
            *(float4*)&Bs[buf^1][bkr*128 + bnc + 4] = nb1;
        }
        __syncthreads();
        buf ^= 1;
    }
    #pragma unroll
    for (int i = 0; i < 4; i++) {
        float* crow = &C[(size_t)(m0 + ty*4 + i) * ldb + col + tx*8];
        #pragma unroll
        for (int j = 0; j < 4; j++) *(float2*)&crow[2*j] = *(float2*)&acc[i][j];
    }
}

// ---------------- generic GEMM + optional residual (double-buffered) ----------------
__global__ __launch_bounds__(256) void sgemm_res(const float* __restrict__ A,
                                                 const float* __restrict__ B,
                                                 float* __restrict__ C,
                                                 const float* __restrict__ res,
                                                 int N, int K) {
    __shared__ float As[2][16*68];
    __shared__ float Bs[2][16*128];
    int n0 = blockIdx.x * 128, m0 = blockIdx.y * 64;
    int tid = threadIdx.x, ty = tid >> 4, tx = tid & 15;
    int amr = tid >> 2, akc = (tid & 3) * 4;
    int bkr = tid >> 4, bnc = (tid & 15) * 8;
    const float* Arow = &A[(size_t)(m0 + amr) * K];
    const float* Bp0 = &B[(size_t)bkr * N + n0 + bnc];
    u64 acc[4][4] = {};
    {
        float4 av = *(const float4*)&Arow[akc];
        float4 b0 = *(const float4*)Bp0;
        float4 b1 = *(const float4*)(Bp0 + 4);
        STORE_A(As[0], av);
        *(float4*)&Bs[0][bkr*128 + bnc]     = b0;
        *(float4*)&Bs[0][bkr*128 + bnc + 4] = b1;
    }
    __syncthreads();
    int buf = 0;
    for (int k0 = 16; k0 <= K; k0 += 16) {
        float4 nav, nb0, nb1;
        bool more = (k0 < K);
        if (more) {
            nav = *(const float4*)&Arow[k0 + akc];
            const float* bp = Bp0 + (size_t)k0 * N;
            nb0 = *(const float4*)bp;
            nb1 = *(const float4*)(bp + 4);
        }
        #pragma unroll
        for (int k = 0; k < 16; k++) GEMM_K_STEP(As[buf], Bs[buf])
        if (more) {
            STORE_A(As[buf^1], nav);
            *(float4*)&Bs[buf^1][bkr*128 + bnc]     = nb0;
            *(float4*)&Bs[buf^1][bkr*128 + bnc + 4] = nb1;
        }
        __syncthreads();
        buf ^= 1;
    }
    #pragma unroll
    for (int i = 0; i < 4; i++) {
        size_t ridx = (size_t)(m0 + ty*4 + i) * N + n0 + tx*8;
        if (res) {
            #pragma unroll
            for (int j = 0; j < 4; j++) {
                u64 rv = *(const u64*)&res[ridx + 2*j];
                u64 s = ad2(acc[i][j], rv);
                *(float2*)&C[ridx + 2*j] = *(float2*)&s;
            }
        } else {
            #pragma unroll
            for (int j = 0; j < 4; j++) *(float2*)&C[ridx + 2*j] = *(float2*)&acc[i][j];
        }
    }
}

// ---------------- shared expert dual GEMM (double-buffered) ----------------
__global__ __launch_bounds__(256) void dual_shared(const float* __restrict__ A,
                                                   const float* __restrict__ B1,
                                                   const float* __restrict__ B2) {
    __shared__ float As[2][16*68];
    __shared__ float B1s[2][16*64];
    __shared__ float B2s[2][16*64];
    int n0 = blockIdx.x * 64, m0 = blockIdx.y * 64;
    int tid = threadIdx.x, ty = tid >> 4, tx = tid & 15;
    int amr = tid >> 2, akc = (tid & 3) * 4;
    int bkr = tid >> 4, bnc = (tid & 15) * 4;
    const float* Arow = &A[(size_t)(m0 + amr) * DM];
    const float* B1p0 = &B1[(size_t)bkr * HE + n0 + bnc];
    const float* B2p0 = &B2[(size_t)bkr * HE + n0 + bnc];
    u64 acc1[4][2] = {}; u64 acc3[4][2] = {};
    {
        float4 av = *(const float4*)&Arow[akc];
        float4 b1 = *(const float4*)B1p0;
        float4 b2 = *(const float4*)B2p0;
        STORE_A(As[0], av);
        *(float4*)&B1s[0][bkr*64 + bnc] = b1;
        *(float4*)&B2s[0][bkr*64 + bnc] = b2;
    }
    __syncthreads();
    int buf = 0;
    for (int k0 = 16; k0 <= DM; k0 += 16) {
        float4 nav, nb1, nb2;
        bool more = (k0 < DM);
        if (more) {
            nav = *(const float4*)&Arow[k0 + akc];
            nb1 = *(const float4*)(B1p0 + (size_t)k0 * HE);
            nb2 = *(const float4*)(B2p0 + (size_t)k0 * HE);
        }
        #pragma unroll
        for (int k = 0; k < 16; k++) {
            float4 a = *(const float4*)&As[buf][k*68 + ty*4];
            u64 pa0 = pk2(a.x), pa1 = pk2(a.y), pa2 = pk2(a.z), pa3 = pk2(a.w);
            ulonglong2 r1 = *(const ulonglong2*)&B1s[buf][k*64 + tx*4];
            ulonglong2 r2 = *(const ulonglong2*)&B2s[buf][k*64 + tx*4];
            fm2(acc1[0][0],pa0,r1.x); fm2(acc1[0][1],pa0,r1.y);
            fm2(acc1[1][0],pa1,r1.x); fm2(acc1[1][1],pa1,r1.y);
            fm2(acc1[2][0],pa2,r1.x); fm2(acc1[2][1],pa2,r1.y);
            fm2(acc1[3][0],pa3,r1.x); fm2(acc1[3][1],pa3,r1.y);
            fm2(acc3[0][0],pa0,r2.x); fm2(acc3[0][1],pa0,r2.y);
            fm2(acc3[1][0],pa1,r2.x); fm2(acc3[1][1],pa1,r2.y);
            fm2(acc3[2][0],pa2,r2.x); fm2(acc3[2][1],pa2,r2.y);
            fm2(acc3[3][0],pa3,r2.x); fm2(acc3[3][1],pa3,r2.y);
        }
        if (more) {
            STORE_A(As[buf^1], nav);
            *(float4*)&B1s[buf^1][bkr*64 + bnc] = nb1;
            *(float4*)&B2s[buf^1][bkr*64 + bnc] = nb2;
        }
        __syncthreads();
        buf ^= 1;
    }
    #pragma unroll
    for (int i = 0; i < 4; i++) {
        float* crow = &g_a1[(size_t)(m0 + ty*4 + i) * HE + n0 + tx*4];
        #pragma unroll
        for (int p = 0; p < 2; p++) {
            float x0,x1,y0,y1;
            up2(x0,x1,acc1[i][p]); up2(y0,y1,acc3[i][p]);
            float2 o;
            o.x = (x0/(1.f+__expf(-x0))) * y0;
            o.y = (x1/(1.f+__expf(-x1))) * y1;
            *(float2*)&crow[2*p] = o;
        }
    }
}

// ---------------- q/k rmsnorm + rope ----------------
__global__ __launch_bounds__(256) void qknorm_rope(const float* __restrict__ qw,
                                                   const float* __restrict__ kw,
                                                   const float* __restrict__ cosb,
                                                   const float* __restrict__ sinb) {
    int gw = (blockIdx.x * blockDim.x + threadIdx.x) >> 5;
    int lane = threadIdx.x & 31;
    if (gw >= SS * (NHQ + NKVH)) return;
    int t = gw / (NHQ + NKVH);
    int hh = gw % (NHQ + NKVH);
    float* base;
    const float* w;
    if (hh < NHQ) { base = &g_q[(size_t)t*(NHQ*HDIM) + hh*HDIM]; w = qw; }
    else          { base = &g_k[(size_t)t*(NKVH*HDIM) + (hh-NHQ)*HDIM]; w = kw; }
    int d0 = lane * 2;
    float v0 = base[d0], v1 = base[d0+1];
    float ss = v0*v0 + v1*v1;
    #pragma unroll
    for (int off = 16; off; off >>= 1) ss += __shfl_xor_sync(0xffffffffu, ss, off);
    float r = rsqrtf(ss * (1.0f/HDIM) + 1e-5f);
    float n0 = v0 * r * w[d0];
    float n1 = v1 * r * w[d0+1];
    float c = cosb[t*(HDIM/2) + lane];
    float s = sinb[t*(HDIM/2) + lane];
    base[d0]   = n0*c - n1*s;
    base[d0+1] = n0*s + n1*c;
}

// ---------------- flash attention (heavy blocks first) ----------------
#define FLASH_SMEM (4*64*65*4)
__global__ __launch_bounds__(256) void flash_attn() {
    extern __shared__ float sm[];
    float* Qs = sm;
    float* Ks = sm + 64*65;
    float* Vs = sm + 2*64*65;
    float* Ps = sm + 3*64*65;
    int qt = (int)gridDim.x - 1 - (int)blockIdx.x;   // heavy (large qt) first
    int h = blockIdx.y;
    int kvh = h >> 2;
    int q0 = qt * 64;
    int tid = threadIdx.x;
    int tx = tid & 15, ty = tid >> 4;
    {
        int r = tid >> 2, c = (tid & 3) * 16;
        const float* src = &g_q[(size_t)(q0 + r)*(NHQ*HDIM) + h*HDIM + c];
        #pragma unroll
        for (int i = 0; i < 16; i += 4) {
            float4 vq = *(const float4*)(src + i);
            Qs[r*65+c+i]   = vq.x; Qs[r*65+c+i+1] = vq.y;
            Qs[r*65+c+i+2] = vq.z; Qs[r*65+c+i+3] = vq.w;
        }
    }
    float O[4][4] = {};
    float m_i[4] = {-1e30f,-1e30f,-1e30f,-1e30f};
    float l_i[4] = {};
    __syncthreads();
    for (int kt = 0; kt <= qt; kt++) {
        int k0 = kt * 64;
        {
            int r = tid >> 2, c = (tid & 3) * 16;
            const float* ksrc = &g_k[(size_t)(k0 + r)*(NKVH*HDIM) + kvh*HDIM + c];
            const float* vsrc = &g_v[(size_t)(k0 + r)*(NKVH*HDIM) + kvh*HDIM + c];
            #pragma unroll
            for (int i = 0; i < 16; i += 4) {
                float4 a = *(const float4*)(ksrc + i);
                float4 b = *(const float4*)(vsrc + i);
                Ks[r*65+c+i]=a.x; Ks[r*65+c+i+1]=a.y; Ks[r*65+c+i+2]=a.z; Ks[r*65+c+i+3]=a.w;
                Vs[r*65+c+i]=b.x; Vs[r*65+c+i+1]=b.y; Vs[r*65+c+i+2]=b.z; Vs[r*65+c+i+3]=b.w;
            }
        }
        __syncthreads();
        float s[4][4] = {};
        #pragma unroll 8
        for (int d = 0; d < 64; d++) {
            float qv[4], kv[4];
            #pragma unroll
            for (int i = 0; i < 4; i++) qv[i] = Qs[(ty*4+i)*65 + d];
            #pragma unroll
            for (int j = 0; j < 4; j++) kv[j] = Ks[(tx*4+j)*65 + d];
            #pragma unroll
            for (int i = 0; i < 4; i++)
                #pragma unroll
                for (int j = 0; j < 4; j++)
                    s[i][j] += qv[i]*kv[j];
        }
        const float sc = 0.125f;
        if (kt == qt) {
            #pragma unroll
            for (int i = 0; i < 4; i++)
                #pragma unroll
                for (int j = 0; j < 4; j++)
                    s[i][j] = (tx*4+j <= ty*4+i) ? s[i][j]*sc : -1e30f;
        } else {
            #pragma unroll
            for (int i = 0; i < 4; i++)
                #pragma unroll
                for (int j = 0; j < 4; j++)
                    s[i][j] *= sc;
        }
        #pragma unroll
        for (int i = 0; i < 4; i++) {
            float mx = fmaxf(fmaxf(s[i][0],s[i][1]), fmaxf(s[i][2],s[i][3]));
            mx = fmaxf(mx, __shfl_xor_sync(0xffffffffu, mx, 1));
            mx = fmaxf(mx, __shfl_xor_sync(0xffffffffu, mx, 2));
            mx = fmaxf(mx, __shfl_xor_sync(0xffffffffu, mx, 4));
            mx = fmaxf(mx, __shfl_xor_sync(0xffffffffu, mx, 8));
            float mn = fmaxf(m_i[i], mx);
            float scale = __expf(m_i[i] - mn);
            float rs = 0.f;
            #pragma unroll
            for (int j = 0; j < 4; j++) { float p = __expf(s[i][j]-mn); s[i][j]=p; rs += p; }
            rs += __shfl_xor_sync(0xffffffffu, rs, 1);
            rs += __shfl_xor_sync(0xffffffffu, rs, 2);
            rs += __shfl_xor_sync(0xffffffffu, rs, 4);
            rs += __shfl_xor_sync(0xffffffffu, rs, 8);
            l_i[i] = l_i[i]*scale + rs;
            m_i[i] = mn;
            #pragma unroll
            for (int j = 0; j < 4; j++) {
                O[i][j] *= scale;
                Ps[(ty*4+i)*65 + tx*4+j] = s[i][j];
            }
        }
        __syncthreads();
        #pragma unroll 4
        for (int jj = 0; jj < 64; jj++) {
            float pv[4], vv[4];
            #pragma unroll
            for (int i = 0; i < 4; i++) pv[i] = Ps[(ty*4+i)*65 + jj];
            #pragma unroll
            for (int j = 0; j < 4; j++) vv[j] = Vs[jj*65 + tx*4+j];
            #pragma unroll
            for (int i = 0; i < 4; i++)
                #pragma unroll
                for (int j = 0; j < 4; j++)
                    O[i][j] += pv[i]*vv[j];
        }
        __syncthreads();
    }
    #pragma unroll
    for (int i = 0; i < 4; i++) {
        float inv = 1.f / l_i[i];
        #pragma unroll
        for (int j = 0; j < 4; j++)
            g_attn[(size_t)(q0+ty*4+i)*(NHQ*HDIM) + h*HDIM + tx*4+j] = O[i][j]*inv;
    }
}

// ---------------- gate GEMM (small N=64) ----------------
__global__ __launch_bounds__(256) void gemm64(const float* __restrict__ A,
                                              const float* __restrict__ B,
                                              float* __restrict__ C,
                                              int M, int N, int K) {
    __shared__ float As[16][64];
    __shared__ float Bs[16][64];
    int tid = threadIdx.x;
    int tx = tid & 15, ty = tid >> 4;
    int m0 = blockIdx.y * 64, n0 = blockIdx.x * 64;
    int ar = tid >> 2;
    int ac = (tid & 3) * 4;
    int br = tid >> 4;
    int bc = (tid & 15) * 4;
    float acc[4][4] = {};
    for (int k0 = 0; k0 < K; k0 += 16) {
        float4 av = *(const float4*)&A[(size_t)(m0 + ar)*K + k0 + ac];
        float4 bv = *(const float4*)&B[(size_t)(k0 + br)*N + n0 + bc];
        As[ac+0][ar] = av.x; As[ac+1][ar] = av.y;
        As[ac+2][ar] = av.z; As[ac+3][ar] = av.w;
        *(float4*)&Bs[br][bc] = bv;
        __syncthreads();
        #pragma unroll
        for (int k = 0; k < 16; k++) {
            float4 a = *(const float4*)&As[k][ty*4];
            float4 b = *(const float4*)&Bs[k][tx*4];
            float aa[4] = {a.x,a.y,a.z,a.w};
            float bb[4] = {b.x,b.y,b.z,b.w};
            #pragma unroll
            for (int i = 0; i < 4; i++)
                #pragma unroll
                for (int j = 0; j < 4; j++)
                    acc[i][j] += aa[i]*bb[j];
        }
        __syncthreads();
    }
    #pragma unroll
    for (int i = 0; i < 4; i++) {
        float4 ov = make_float4(acc[i][0],acc[i][1],acc[i][2],acc[i][3]);
        *(float4*)&C[(size_t)(m0 + ty*4 + i)*N + n0 + tx*4] = ov;
    }
}

// ---------------- routing ----------------
__global__ void zero_cnt_k() { if (threadIdx.x < NE) g_cnt[threadIdx.x] = 0; }

__global__ void route_k() {
    int t = blockIdx.x;
    int lane = threadIdx.x;
    float v0 = g_logits[t*NE + lane];
    float v1 = g_logits[t*NE + 32 + lane];
    float selv[TOPK]; int seli[TOPK];
    #pragma unroll
    for (int it = 0; it < TOPK; it++) {
        float best = (v0 >= v1) ? v0 : v1;
        int   bi   = (v0 >= v1) ? lane : lane + 32;
        #pragma unroll
        for (int off = 16; off; off >>= 1) {
            float ov = __shfl_xor_sync(0xffffffffu, best, off);
            int   oi = __shfl_xor_sync(0xffffffffu, bi, off);
            if (ov > best || (ov == best && oi < bi)) { best = ov; bi = oi; }
        }
        selv[it] = best; seli[it] = bi;
        if (bi == lane)      v0 = -1e30f;
        if (bi == lane + 32) v1 = -1e30f;
    }
    if (lane < TOPK) {
        float sum = 0.f;
        #pragma unroll
        for (int i = 0; i < TOPK; i++) sum += __expf(selv[i] - selv[0]);
        float w = __expf(selv[lane] - selv[0]) / sum;
        int e = seli[lane];
        int pos = atomicAdd(&g_cnt[e], 1);
        g_list[e*SS + pos] = t*TOPK + lane;
        g_pairw[t*TOPK + lane] = w;
    }
}

// ---------------- MoE GEMM1 (grouped dual, double-buffered) ----------------
__global__ __launch_bounds__(256) void moe_gemm1(const float* __restrict__ w1e,
                                                 const float* __restrict__ w3e) {
    int e  = blockIdx.x >> 3;
    int n0 = (blockIdx.x & 7) * 64;
    int n = g_cnt[e];
    if (n == 0) return;
    const int* lst = &g_list[e*SS];
    const float* W1 = w1e + (size_t)e * DM * HE;
    const float* W3 = w3e + (size_t)e * DM * HE;
    __shared__ float As[2][16*68];
    __shared__ float B1s[2][16*64];
    __shared__ float B2s[2][16*64];
    __shared__ int s_p[64];
    int tid = threadIdx.x, ty = tid >> 4, tx = tid & 15;
    int amr = tid >> 2, akc = (tid & 3) * 4;
    int bkr = tid >> 4, bnc = (tid & 15) * 4;
    const float* B1p0 = &W1[(size_t)bkr * HE + n0 + bnc];
    const float* B2p0 = &W3[(size_t)bkr * HE + n0 + bnc];
    for (int m0 = 0; m0 < n; m0 += 64) {
        if (tid < 64) s_p[tid] = (m0 + tid < n) ? lst[m0 + tid] : -1;
        __syncthreads();
        int pz = s_p[amr];
        const float* Arow = &g_z[(size_t)(pz < 0 ? 0 : pz / TOPK) * DM];
        u64 acc1[4][2] = {}; u64 acc3[4][2] = {};
        {
            float4 av = *(const float4*)&Arow[akc];
            float4 b1 = *(const float4*)B1p0;
            float4 b2 = *(const float4*)B2p0;
            STORE_A(As[0], av);
            *(float4*)&B1s[0][bkr*64 + bnc] = b1;
            *(float4*)&B2s[0][bkr*64 + bnc] = b2;
        }
        __syncthreads();
        int buf = 0;
        for (int k0 = 16; k0 <= DM; k0 += 16) {
            float4 nav, nb1, nb2;
            bool more = (k0 < DM);
            if (more) {
                nav = *(const float4*)&Arow[k0 + akc];
                nb1 = *(const float4*)(B1p0 + (size_t)k0 * HE);
                nb2 = *(const float4*)(B2p0 + (size_t)k0 * HE);
            }
            #pragma unroll
            for (int k = 0; k < 16; k++) {
                float4 a = *(const float4*)&As[buf][k*68 + ty*4];
                u64 pa0 = pk2(a.x), pa1 = pk2(a.y), pa2 = pk2(a.z), pa3 = pk2(a.w);
                ulonglong2 r1 = *(const ulonglong2*)&B1s[buf][k*64 + tx*4];
                ulonglong2 r2 = *(const ulonglong2*)&B2s[buf][k*64 + tx*4];
                fm2(acc1[0][0],pa0,r1.x); fm2(acc1[0][1],pa0,r1.y);
                fm2(acc1[1][0],pa1,r1.x); fm2(acc1[1][1],pa1,r1.y);
                fm2(acc1[2][0],pa2,r1.x); fm2(acc1[2][1],pa2,r1.y);
                fm2(acc1[3][0],pa3,r1.x); fm2(acc1[3][1],pa3,r1.y);
                fm2(acc3[0][0],pa0,r2.x); fm2(acc3[0][1],pa0,r2.y);
                fm2(acc3[1][0],pa1,r2.x); fm2(acc3[1][1],pa1,r2.y);
                fm2(acc3[2][0],pa2,r2.x); fm2(acc3[2][1],pa2,r2.y);
                fm2(acc3[3][0],pa3,r2.x); fm2(acc3[3][1],pa3,r2.y);
            }
            if (more) {
                STORE_A(As[buf^1], nav);
                *(float4*)&B1s[buf^1][bkr*64 + bnc] = nb1;
                *(float4*)&B2s[buf^1][bkr*64 + bnc] = nb2;
            }
            __syncthreads();
            buf ^= 1;
        }
        #pragma unroll
        for (int i = 0; i < 4; i++) {
            int pr = s_p[ty*4 + i];
            if (pr >= 0) {
                float w = g_pairw[pr];
                float* crow = &g_gbuf[(size_t)pr * HE + n0 + tx*4];
                #pragma unroll
                for (int p = 0; p < 2; p++) {
                    float x0,x1,y0,y1;
                    up2(x0,x1,acc1[i][p]); up2(y0,y1,acc3[i][p]);
                    float2 o;
                    o.x = (x0/(1.f+__expf(-x0))) * y0 * w;
                    o.y = (x1/(1.f+__expf(-x1))) * y1 * w;
                    *(float2*)&crow[2*p] = o;
                }
            }
        }
        __syncthreads();
    }
}

// ---------------- MoE GEMM2 (grouped, double-buffered) ----------------
__global__ __launch_bounds__(256) void moe_gemm2(const float* __restrict__ w2e) {
    int e  = blockIdx.x >> 3;
    int n0 = (blockIdx.x & 7) * 128;
    int n = g_cnt[e];
    if (n == 0) return;
    const int* lst = &g_list[e*SS];
    const float* W2 = w2e + (size_t)e * HE * DM;
    __shared__ float As[2][16*68];
    __shared__ float Bs[2][16*128];
    __shared__ int s_p[64];
    int tid = threadIdx.x, ty = tid >> 4, tx = tid & 15;
    int amr = tid >> 2, akc = (tid & 3) * 4;
    int bkr = tid >> 4, bnc = (tid & 15) * 8;
    const float* Bp0 = &W2[(size_t)bkr * DM + n0 + bnc];
    for (int m0 = 0; m0 < n; m0 += 64) {
        if (tid < 64) s_p[tid] = (m0 + tid < n) ? lst[m0 + tid] : -1;
        __syncthreads();
        int pz = s_p[amr];
        const float* Arow = &g_gbuf[(size_t)(pz < 0 ? 0 : pz) * HE];
        u64 acc[4][4] = {};
        {
            float4 av = *(const float4*)&Arow[akc];
            float4 b0 = *(const float4*)Bp0;
            float4 b1 = *(const float4*)(Bp0 + 4);
            STORE_A(As[0], av);
            *(float4*)&Bs[0][bkr*128 + bnc]     = b0;
            *(float4*)&Bs[0][bkr*128 + bnc + 4] = b1;
        }
        __syncthreads();
        int buf = 0;
        for (int k0 = 16; k0 <= HE; k0 += 16) {
            float4 nav, nb0, nb1;
            bool more = (k0 < HE);
            if (more) {
                nav = *(const float4*)&Arow[k0 + akc];
                const float* bp = Bp0 + (size_t)k0 * DM;
                nb0 = *(const float4*)bp;
                nb1 = *(const float4*)(bp + 4);
            }
            #pragma unroll
            for (int k = 0; k < 16; k++) GEMM_K_STEP(As[buf], Bs[buf])
            if (more) {
                STORE_A(As[buf^1], nav);
                *(float4*)&Bs[buf^1][bkr*128 + bnc]     = nb0;
                *(float4*)&Bs[buf^1][bkr*128 + bnc + 4] = nb1;
            }
            __syncthreads();
            buf ^= 1;
        }
        #pragma unroll
        for (int i = 0; i < 4; i++) {
            int pr = s_p[ty*4 + i];
            if (pr >= 0) {
                float* crow = &g_g2[(size_t)pr * DM + n0 + tx*8];
                #pragma unroll
                for (int j = 0; j < 4; j++) *(float2*)&crow[2*j] = *(float2*)&acc[i][j];
            }
        }
        __syncthreads();
    }
}

// ---------------- final: out = h + shared + sum_k g2[t*6+k] ----------------
__global__ __launch_bounds__(256) void final_k(float* __restrict__ out) {
    int t = blockIdx.x;
    int c = threadIdx.x * 4;
    float4 a = *(const float4*)&g_h[(size_t)t*DM + c];
    float4 b = *(const float4*)&g_sh[(size_t)t*DM + c];
    a.x += b.x; a.y += b.y; a.z += b.z; a.w += b.w;
    #pragma unroll
    for (int kk = 0; kk < TOPK; kk++) {
        float4 gv = *(const float4*)&g_g2[(size_t)(t*TOPK+kk)*DM + c];
        a.x += gv.x; a.y += gv.y; a.z += gv.z; a.w += gv.w;
    }
    *(float4*)&out[(size_t)t*DM + c] = a;
}

// ---------------- host ----------------
extern "C" void kernel_launch(void* const* d_in, const int* in_sizes, int n_in,
                              void* d_out, int out_size) {
    const float* x   = (const float*)d_in[0];
    const float* fc  = (const float*)d_in[1];
    const float* fs  = (const float*)d_in[2];
    const float* anw = (const float*)d_in[3];
    const float* fnw = (const float*)d_in[4];
    const float* wq  = (const float*)d_in[5];
    const float* wk  = (const float*)d_in[6];
    const float* wv  = (const float*)d_in[7];
    const float* wo  = (const float*)d_in[8];
    const float* qnw = (const float*)d_in[9];
    const float* knw = (const float*)d_in[10];
    const float* gw  = (const float*)d_in[11];
    const float* w1e = (const float*)d_in[12];
    const float* w3e = (const float*)d_in[13];
    const float* w2e = (const float*)d_in[14];
    const float* sw1 = (const float*)d_in[15];
    const float* sw3 = (const float*)d_in[16];
    const float* sw2 = (const float*)d_in[17];
    float* out = (float*)d_out;

    float *hx,*attn,*h,*z,*logits,*a1,*sh;
    cudaGetSymbolAddress((void**)&hx, g_hx);
    cudaGetSymbolAddress((void**)&attn, g_attn);
    cudaGetSymbolAddress((void**)&h,  g_h);
    cudaGetSymbolAddress((void**)&z,  g_z);
    cudaGetSymbolAddress((void**)&logits, g_logits);
    cudaGetSymbolAddress((void**)&a1, g_a1);
    cudaGetSymbolAddress((void**)&sh, g_sh);

    cudaFuncSetAttribute(flash_attn, cudaFuncAttributeMaxDynamicSharedMemorySize, FLASH_SMEM);

    // attention branch
    rmsnorm_k<<<SS, 256>>>(x, anw, hx);
    qkv_gemm<<<dim3(12, 16), 256>>>(hx, wq, wk, wv);
    qknorm_rope<<<(SS*(NHQ+NKVH)*32)/256, 256>>>(qnw, knw, fc, fs);
    flash_attn<<<dim3(16,16), 256, FLASH_SMEM>>>();
    sgemm_res<<<dim3(8, 16), 256>>>(attn, wo, h, x, 1024, 1024);   // h = attn@wo + x

    // ffn branch
    rmsnorm_k<<<SS, 256>>>(h, fnw, z);
    gemm64<<<dim3(1, 16), 256>>>(z, gw, logits, SS, NE, DM);
    zero_cnt_k<<<1, 64>>>();
    route_k<<<SS, 32>>>();
    moe_gemm1<<<NE*8, 256>>>(w1e, w3e);
    moe_gemm2<<<NE*8, 256>>>(w2e);

    // shared expert (silu*mul fused into dual GEMM epilogue)
    dual_shared<<<dim3(8, 16), 256>>>(z, sw1, sw3);
    sgemm_res<<<dim3(8, 16), 256>>>(a1, sw2, sh, nullptr, 1024, 512);

    final_k<<<SS, 256>>>(out);
}